// round 13
// baseline (speedup 1.0000x reference)
#include <cuda_runtime.h>
#include <cuda_bf16.h>

// Batched Kalman update: B=262144, DX=8, DZ=4.  TWO threads per batch.
// Pair = lanes (2m, 2m+1); thread h owns rows 4h..4h+3 (no rotation).
//
// Conflict-free even-stride trick (SREG=18): every row access touches its two
// quads in h-swapped order -- Buf4[A+h] then Buf4[A+1-h] -- so h0 lanes hit
// even quads while h1 lanes hit odd quads in the same instruction; with
// stride 18 the phase address sets are disjoint -> no bank conflicts, and
// qa always holds own-row cols 4h..4h+3 so ALL epilogue indices are static.
//
// SREG=18 => region == output record [x(2q)|P(16q)]; block results form one
// contiguous 18KB span drained by a single cp.async.bulk (TMA pipe).
//
// W-form math (== Joseph form for the optimal gain):
//   PHT = P H^T, S = H PHT + R = L L^T;  W = PHT L^-T,  u = L^-1 y
//   x_new = x + W u,  P_new = P - W W^T
//
// vs R12: epilogue one row at a time (po[8]) -> register peak ~52, and
// __launch_bounds__(128, 9): 9 CTAs/SM = 36 warps (56% occ) now that the
// L1 wall (55%) no longer binds.

#define NT   128
#define BPB  64
#define SREG 18

__global__ void __launch_bounds__(NT, 9) kalman_kernel(
    const float4* __restrict__ x4,
    const float4* __restrict__ z4,
    const float4* __restrict__ P4,
    const float*  __restrict__ Hg,
    const float*  __restrict__ Rg,
    float4*       __restrict__ out4,
    int nb)
{
    __shared__ float4 Buf4[BPB * SREG];   // 18432 B, contiguous output image
    __shared__ float4 HT4[8];             // HT4[k] = H[0..3][k]
    __shared__ float  Rs[16];

    const int t   = threadIdx.x;
    const int b0  = blockIdx.x * BPB;
    const int nbb = min(BPB, nb - b0);

    if (t < 8)  HT4[t] = make_float4(Hg[t], Hg[8 + t], Hg[16 + t], Hg[24 + t]);
    if (t >= 32 && t < 48) Rs[t - 32] = Rg[t - 32];

    // ---- Stage P: coalesced LDG.128, conflict-free STS.128 ----
    {
        const int hw = t >> 4;            // half-warp id 0..7
        const int fq = t & 15;            // quad-in-record
        #pragma unroll
        for (int k = 0; k < 8; k++) {
            int m = hw + 8 * k;
            if (m < nbb)
                Buf4[m * SREG + 2 + fq] = P4[(size_t)b0 * 16 + 16 * m + fq];
        }
    }

    // ---- Direct loads: x quad (elems 4h..4h+3) on its owner; z per pair ----
    float4 xq = make_float4(0.f, 0.f, 0.f, 0.f);
    float4 zq = make_float4(0.f, 0.f, 0.f, 0.f);
    if (t < 2 * nbb) {
        xq = x4[(size_t)b0 * 2 + t];
        zq = z4[b0 + (t >> 1)];
    }

    __syncthreads();

    if (t < 2 * nbb) {
        const int m  = t >> 1;
        const int h  = t & 1;
        const int rb = m * SREG;
        const int hb1 = 4 * h;            // HT base for qa cols (own)
        const int hb2 = 4 - 4 * h;        // HT base for qb cols (partner)
        const unsigned FM = 0xffffffffu;

        // ---- y = z - H x (pair-partial; own elems are cols 4h..4h+3) ----
        float xo0 = xq.x, xo1 = xq.y, xo2 = xq.z, xo3 = xq.w;
        float s0, s1, s2, s3;
        {
            float4 ha = HT4[hb1 + 0], hb = HT4[hb1 + 1];
            float4 hc = HT4[hb1 + 2], hd = HT4[hb1 + 3];
            s0 = ha.x * xo0 + hb.x * xo1 + hc.x * xo2 + hd.x * xo3;
            s1 = ha.y * xo0 + hb.y * xo1 + hc.y * xo2 + hd.y * xo3;
            s2 = ha.z * xo0 + hb.z * xo1 + hc.z * xo2 + hd.z * xo3;
            s3 = ha.w * xo0 + hb.w * xo1 + hc.w * xo2 + hd.w * xo3;
        }
        float y0 = zq.x - (s0 + __shfl_xor_sync(FM, s0, 1));
        float y1 = zq.y - (s1 + __shfl_xor_sync(FM, s1, 1));
        float y2 = zq.z - (s2 + __shfl_xor_sync(FM, s2, 1));
        float y3 = zq.w - (s3 + __shfl_xor_sync(FM, s3, 1));

        // ---- W = PHT for own rows 4h+i (parity-swapped quad reads) ----
        float W[4][4];
        #pragma unroll
        for (int i = 0; i < 4; i++) {
            const int A = rb + 2 + 8 * h + 2 * i;   // quad pair base of row 4h+i
            float4 qa = Buf4[A + h];                // cols 4h..4h+3
            float4 qb = Buf4[A + 1 - h];            // cols 4(1-h)..
            float q0, q1, q2, q3;
            {
                float4 c0 = HT4[hb1 + 0], c1 = HT4[hb1 + 1];
                float4 c2 = HT4[hb1 + 2], c3 = HT4[hb1 + 3];
                q0 = qa.x * c0.x + qa.y * c1.x + qa.z * c2.x + qa.w * c3.x;
                q1 = qa.x * c0.y + qa.y * c1.y + qa.z * c2.y + qa.w * c3.y;
                q2 = qa.x * c0.z + qa.y * c1.z + qa.z * c2.z + qa.w * c3.z;
                q3 = qa.x * c0.w + qa.y * c1.w + qa.z * c2.w + qa.w * c3.w;
            }
            {
                float4 c0 = HT4[hb2 + 0], c1 = HT4[hb2 + 1];
                float4 c2 = HT4[hb2 + 2], c3 = HT4[hb2 + 3];
                q0 += qb.x * c0.x + qb.y * c1.x + qb.z * c2.x + qb.w * c3.x;
                q1 += qb.x * c0.y + qb.y * c1.y + qb.z * c2.y + qb.w * c3.y;
                q2 += qb.x * c0.z + qb.y * c1.z + qb.z * c2.z + qb.w * c3.z;
                q3 += qb.x * c0.w + qb.y * c1.w + qb.z * c2.w + qb.w * c3.w;
            }
            W[i][0] = q0; W[i][1] = q1; W[i][2] = q2; W[i][3] = q3;
        }

        // ---- S partial from own rows (row 4h+i -> HT4[4h+i]), pair-reduce ----
        float S00 = 0.f, S01 = 0.f, S02 = 0.f, S03 = 0.f;
        float S11 = 0.f, S12 = 0.f, S13 = 0.f;
        float S22 = 0.f, S23 = 0.f, S33 = 0.f;
        #pragma unroll
        for (int i = 0; i < 4; i++) {
            float4 ht = HT4[hb1 + i];
            float q0 = W[i][0], q1 = W[i][1], q2 = W[i][2], q3 = W[i][3];
            S00 += ht.x * q0; S01 += ht.x * q1; S02 += ht.x * q2; S03 += ht.x * q3;
            S11 += ht.y * q1; S12 += ht.y * q2; S13 += ht.y * q3;
            S22 += ht.z * q2; S23 += ht.z * q3;
            S33 += ht.w * q3;
        }
        S00 += __shfl_xor_sync(FM, S00, 1); S01 += __shfl_xor_sync(FM, S01, 1);
        S02 += __shfl_xor_sync(FM, S02, 1); S03 += __shfl_xor_sync(FM, S03, 1);
        S11 += __shfl_xor_sync(FM, S11, 1); S12 += __shfl_xor_sync(FM, S12, 1);
        S13 += __shfl_xor_sync(FM, S13, 1); S22 += __shfl_xor_sync(FM, S22, 1);
        S23 += __shfl_xor_sync(FM, S23, 1); S33 += __shfl_xor_sync(FM, S33, 1);
        S00 += Rs[0];  S01 += Rs[1];  S02 += Rs[2];  S03 += Rs[3];
        S11 += Rs[5];  S12 += Rs[6];  S13 += Rs[7];
        S22 += Rs[10]; S23 += Rs[11]; S33 += Rs[15];

        // ---- Cholesky ----
        float i0  = rsqrtf(S00);
        float l10 = S01 * i0, l20 = S02 * i0, l30 = S03 * i0;
        float i1  = rsqrtf(S11 - l10 * l10);
        float l21 = (S12 - l20 * l10) * i1;
        float l31 = (S13 - l30 * l10) * i1;
        float i2  = rsqrtf(S22 - l20 * l20 - l21 * l21);
        float l32 = (S23 - l30 * l20 - l31 * l21) * i2;
        float i3  = rsqrtf(S33 - l30 * l30 - l31 * l31 - l32 * l32);

        // ---- W <- W L^-T ----
        #pragma unroll
        for (int i = 0; i < 4; i++) {
            float w0 = W[i][0] * i0;
            float w1 = (W[i][1] - l10 * w0) * i1;
            float w2 = (W[i][2] - l20 * w0 - l21 * w1) * i2;
            float w3 = (W[i][3] - l30 * w0 - l31 * w1 - l32 * w2) * i3;
            W[i][0] = w0; W[i][1] = w1; W[i][2] = w2; W[i][3] = w3;
        }

        // ---- u = L^-1 y ----
        float u0 = y0 * i0;
        float u1 = (y1 - l10 * u0) * i1;
        float u2 = (y2 - l20 * u0 - l21 * u1) * i2;
        float u3 = (y3 - l30 * u0 - l31 * u1 - l32 * u2) * i3;

        // ---- x_new own quad: elem 4h+i pairs with own W[i] (static) ----
        Buf4[rb + h] = make_float4(
            xo0 + W[0][0]*u0 + W[0][1]*u1 + W[0][2]*u2 + W[0][3]*u3,
            xo1 + W[1][0]*u0 + W[1][1]*u1 + W[1][2]*u2 + W[1][3]*u3,
            xo2 + W[2][0]*u0 + W[2][1]*u1 + W[2][2]*u2 + W[2][3]*u3,
            xo3 + W[3][0]*u0 + W[3][1]*u1 + W[3][2]*u2 + W[3][3]*u3);

        // ---- Partner W via 16 xor-shuffles: pW[s] = partner row 4(1-h)+s ----
        float pW[4][4];
        #pragma unroll
        for (int s = 0; s < 4; s++)
            #pragma unroll
            for (int c = 0; c < 4; c++)
                pW[s][c] = __shfl_xor_sync(FM, W[s][c], 1);

        // ---- P_new = P - W W^T, ONE row at a time; ALL indices static ----
        // po[c]   = col 4h+c     -> subtract W[i].W[c]   (own rows)
        // po[4+c] = col 4(1-h)+c -> subtract W[i].pW[c]  (partner rows)
        #pragma unroll
        for (int i = 0; i < 4; i++) {
            const int A = rb + 2 + 8 * h + 2 * i;
            float po[8];
            {
                float4 qa = Buf4[A + h];
                float4 qb = Buf4[A + 1 - h];
                po[0] = qa.x; po[1] = qa.y; po[2] = qa.z; po[3] = qa.w;
                po[4] = qb.x; po[5] = qb.y; po[6] = qb.z; po[7] = qb.w;
            }
            float w0 = W[i][0], w1 = W[i][1], w2 = W[i][2], w3 = W[i][3];
            #pragma unroll
            for (int c = 0; c < 4; c++)
                po[c] -= w0 * W[c][0] + w1 * W[c][1]
                       + w2 * W[c][2] + w3 * W[c][3];
            #pragma unroll
            for (int c = 0; c < 4; c++)
                po[4 + c] -= w0 * pW[c][0] + w1 * pW[c][1]
                           + w2 * pW[c][2] + w3 * pW[c][3];
            Buf4[A + h]     = make_float4(po[0], po[1], po[2], po[3]);
            Buf4[A + 1 - h] = make_float4(po[4], po[5], po[6], po[7]);
        }
    }

    __syncthreads();

    // ---- Drain: one contiguous bulk copy SMEM -> GMEM via the TMA pipe ----
    if (t == 0) {
        unsigned sa = (unsigned)__cvta_generic_to_shared(&Buf4[0]);
        float4* gdst = out4 + (size_t)b0 * 18;
        int bytes = nbb * 18 * 16;
        asm volatile("fence.proxy.async.shared::cta;" ::: "memory");
        asm volatile(
            "cp.async.bulk.global.shared::cta.bulk_group [%0], [%1], %2;"
            :: "l"(gdst), "r"(sa), "r"(bytes) : "memory");
        asm volatile("cp.async.bulk.commit_group;" ::: "memory");
        asm volatile("cp.async.bulk.wait_group.read 0;" ::: "memory");
    }
}

extern "C" void kernel_launch(void* const* d_in, const int* in_sizes, int n_in,
                              void* d_out, int out_size) {
    const float4* x4 = (const float4*)d_in[0];
    const float4* z4 = (const float4*)d_in[1];
    const float4* P4 = (const float4*)d_in[2];
    const float*  Hg = (const float*)d_in[3];
    const float*  Rg = (const float*)d_in[4];
    float4* out4 = (float4*)d_out;

    int nb = in_sizes[0] / 8;            // B
    int grid = (nb + BPB - 1) / BPB;
    kalman_kernel<<<grid, NT>>>(x4, z4, P4, Hg, Rg, out4, nb);
}